// round 1
// baseline (speedup 1.0000x reference)
#include <cuda_runtime.h>
#include <cuda_bf16.h>
#include <cstdint>

#define DIN  4096
#define DOUT 4096
#define MTOT 8192   // 4 * 2048 rows

// ---------------- scratch (device globals: allocation-free rule) -------------
__device__ __align__(16) __nv_bfloat16 g_Ahi[(size_t)MTOT * DIN];   // 64 MB
__device__ __align__(16) __nv_bfloat16 g_Alo[(size_t)MTOT * DIN];   // 64 MB
__device__ __align__(16) __nv_bfloat16 g_W  [(size_t)DOUT * DIN];   // 32 MB
__device__ double g_psum[256];
__device__ double g_pabs[DOUT];
__device__ float  g_mu;
__device__ float  g_beta;

__device__ __forceinline__ unsigned short bfbits(float f) {
    __nv_bfloat16 h = __float2bfloat16(f);
    return *reinterpret_cast<unsigned short*>(&h);
}

// ---------------- 1) weight sum (fp64 two-stage, deterministic) --------------
__global__ __launch_bounds__(256) void kwsum(const float4* __restrict__ w) {
    int t = blockIdx.x * 256 + threadIdx.x;   // 65536 threads, 64 float4 each
    double acc = 0.0;
#pragma unroll 4
    for (int i = 0; i < 64; i++) {
        float4 v = w[t + i * 65536];
        acc += (double)v.x + (double)v.y + (double)v.z + (double)v.w;
    }
    __shared__ double sd[256];
    sd[threadIdx.x] = acc; __syncthreads();
    for (int s = 128; s > 0; s >>= 1) {
        if (threadIdx.x < s) sd[threadIdx.x] += sd[threadIdx.x + s];
        __syncthreads();
    }
    if (threadIdx.x == 0) g_psum[blockIdx.x] = sd[0];
}

__global__ void kmu() {
    __shared__ double sd[256];
    sd[threadIdx.x] = g_psum[threadIdx.x]; __syncthreads();
    for (int s = 128; s > 0; s >>= 1) {
        if (threadIdx.x < s) sd[threadIdx.x] += sd[threadIdx.x + s];
        __syncthreads();
    }
    if (threadIdx.x == 0) g_mu = (float)(sd[0] * (1.0 / 16777216.0));
}

// ---------------- 2) binarize weights + |w-mu| row sums ----------------------
__global__ __launch_bounds__(256) void kbin(const float* __restrict__ w) {
    int row = blockIdx.x;
    int tid = threadIdx.x;
    float mu = g_mu;
    const float4* wr = (const float4*)(w + (size_t)row * DIN);
    uint2* wb = (uint2*)(g_W + (size_t)row * DIN);
    double acc = 0.0;
#pragma unroll
    for (int j = 0; j < 4; j++) {
        int idx = tid + j * 256;
        float4 v = wr[idx];
        float d0 = v.x - mu, d1 = v.y - mu, d2 = v.z - mu, d3 = v.w - mu;
        acc += (double)fabsf(d0); acc += (double)fabsf(d1);
        acc += (double)fabsf(d2); acc += (double)fabsf(d3);
        float s0 = (d0 > 0.f) ? 1.f : ((d0 < 0.f) ? -1.f : 0.f);
        float s1 = (d1 > 0.f) ? 1.f : ((d1 < 0.f) ? -1.f : 0.f);
        float s2 = (d2 > 0.f) ? 1.f : ((d2 < 0.f) ? -1.f : 0.f);
        float s3 = (d3 > 0.f) ? 1.f : ((d3 < 0.f) ? -1.f : 0.f);
        uint2 o;
        o.x = (uint32_t)bfbits(s0) | ((uint32_t)bfbits(s1) << 16);
        o.y = (uint32_t)bfbits(s2) | ((uint32_t)bfbits(s3) << 16);
        wb[idx] = o;
    }
    __shared__ double sd[256];
    sd[tid] = acc; __syncthreads();
    for (int s = 128; s > 0; s >>= 1) {
        if (tid < s) sd[tid] += sd[tid + s];
        __syncthreads();
    }
    if (tid == 0) g_pabs[row] = sd[0];
}

__global__ void kbeta() {
    __shared__ double sd[1024];
    int t = threadIdx.x;
    double a = g_pabs[t] + g_pabs[t + 1024] + g_pabs[t + 2048] + g_pabs[t + 3072];
    sd[t] = a; __syncthreads();
    for (int s = 512; s > 0; s >>= 1) {
        if (t < s) sd[t] += sd[t + s];
        __syncthreads();
    }
    if (t == 0) g_beta = (float)(sd[0] * (1.0 / 16777216.0));
}

// ---------------- 3) LayerNorm + hi/lo bf16 split -----------------------------
__global__ __launch_bounds__(256) void kln(const float* __restrict__ x) {
    int row = blockIdx.x;
    int tid = threadIdx.x;
    const float4* xr = (const float4*)(x + (size_t)row * DIN);
    float4 v[4];
    float s = 0.f, ss = 0.f;
#pragma unroll
    for (int j = 0; j < 4; j++) {
        v[j] = xr[tid + j * 256];
        s  += v[j].x + v[j].y + v[j].z + v[j].w;
        ss += v[j].x * v[j].x + v[j].y * v[j].y + v[j].z * v[j].z + v[j].w * v[j].w;
    }
#pragma unroll
    for (int o = 16; o > 0; o >>= 1) {
        s  += __shfl_down_sync(0xffffffffu, s,  o);
        ss += __shfl_down_sync(0xffffffffu, ss, o);
    }
    __shared__ float sh_s[8], sh_ss[8];
    if ((tid & 31) == 0) { sh_s[tid >> 5] = s; sh_ss[tid >> 5] = ss; }
    __syncthreads();
    float ts = 0.f, tss = 0.f;
#pragma unroll
    for (int i = 0; i < 8; i++) { ts += sh_s[i]; tss += sh_ss[i]; }
    float mu   = ts * (1.f / 4096.f);
    float var  = tss * (1.f / 4096.f) - mu * mu;
    float rstd = rsqrtf(var + 1e-5f);

    uint2* ph = (uint2*)(g_Ahi + (size_t)row * DIN);
    uint2* pl = (uint2*)(g_Alo + (size_t)row * DIN);
#pragma unroll
    for (int j = 0; j < 4; j++) {
        int idx = tid + j * 256;
        float xn0 = (v[j].x - mu) * rstd;
        float xn1 = (v[j].y - mu) * rstd;
        float xn2 = (v[j].z - mu) * rstd;
        float xn3 = (v[j].w - mu) * rstd;
        unsigned short h0 = bfbits(xn0), h1 = bfbits(xn1), h2 = bfbits(xn2), h3 = bfbits(xn3);
        __nv_bfloat16 b0 = *reinterpret_cast<__nv_bfloat16*>(&h0);
        __nv_bfloat16 b1 = *reinterpret_cast<__nv_bfloat16*>(&h1);
        __nv_bfloat16 b2 = *reinterpret_cast<__nv_bfloat16*>(&h2);
        __nv_bfloat16 b3 = *reinterpret_cast<__nv_bfloat16*>(&h3);
        float l0 = xn0 - __bfloat162float(b0);
        float l1 = xn1 - __bfloat162float(b1);
        float l2 = xn2 - __bfloat162float(b2);
        float l3 = xn3 - __bfloat162float(b3);
        uint2 oh, ol;
        oh.x = (uint32_t)h0 | ((uint32_t)h1 << 16);
        oh.y = (uint32_t)h2 | ((uint32_t)h3 << 16);
        ol.x = (uint32_t)bfbits(l0) | ((uint32_t)bfbits(l1) << 16);
        ol.y = (uint32_t)bfbits(l2) | ((uint32_t)bfbits(l3) << 16);
        ph[idx] = oh;
        pl[idx] = ol;
    }
}

// ---------------- 4) GEMM: (A_hi + A_lo) @ Wbin^T, fp32 accum ----------------
#define BM 128
#define BN 128
#define BK 32
#define STR 40   // bf16 smem row stride: 20 words -> conflict-free frag loads

#define MMA(C, A, B0, B1) asm volatile( \
    "mma.sync.aligned.m16n8k16.row.col.f32.bf16.bf16.f32 " \
    "{%0,%1,%2,%3},{%4,%5,%6,%7},{%8,%9},{%0,%1,%2,%3};\n" \
    : "+f"(C[0]), "+f"(C[1]), "+f"(C[2]), "+f"(C[3]) \
    : "r"(A[0]), "r"(A[1]), "r"(A[2]), "r"(A[3]), "r"(B0), "r"(B1))

__global__ __launch_bounds__(256) void kgemm(float* __restrict__ C) {
    __shared__ __nv_bfloat16 sAh[BM * STR];
    __shared__ __nv_bfloat16 sAl[BM * STR];
    __shared__ __nv_bfloat16 sB [BN * STR];

    const int tid  = threadIdx.x;
    const int lane = tid & 31;
    const int warp = tid >> 5;
    const int wm = warp >> 2;     // 0..1 -> 64 rows
    const int wn = warp & 3;      // 0..3 -> 32 cols
    const int m0 = blockIdx.y * BM;
    const int n0 = blockIdx.x * BN;

    float c[4][4][4];
#pragma unroll
    for (int a = 0; a < 4; a++)
#pragma unroll
        for (int b = 0; b < 4; b++)
#pragma unroll
            for (int d = 0; d < 4; d++) c[a][b][d] = 0.f;

    const __nv_bfloat16* Ah = g_Ahi + (size_t)m0 * DIN;
    const __nv_bfloat16* Al = g_Alo + (size_t)m0 * DIN;
    const __nv_bfloat16* Bw = g_W   + (size_t)n0 * DIN;

    const int r0l = (tid + 0)   >> 2, q0l = (tid + 0)   & 3;
    const int r1l = (tid + 256) >> 2, q1l = (tid + 256) & 3;

    for (int k0 = 0; k0 < DIN; k0 += BK) {
        // ---- load tiles (2 x uint4 per thread per matrix) ----
        *(uint4*)(sAh + r0l * STR + q0l * 8) = *(const uint4*)(Ah + (size_t)r0l * DIN + k0 + q0l * 8);
        *(uint4*)(sAh + r1l * STR + q1l * 8) = *(const uint4*)(Ah + (size_t)r1l * DIN + k0 + q1l * 8);
        *(uint4*)(sAl + r0l * STR + q0l * 8) = *(const uint4*)(Al + (size_t)r0l * DIN + k0 + q0l * 8);
        *(uint4*)(sAl + r1l * STR + q1l * 8) = *(const uint4*)(Al + (size_t)r1l * DIN + k0 + q1l * 8);
        *(uint4*)(sB  + r0l * STR + q0l * 8) = *(const uint4*)(Bw + (size_t)r0l * DIN + k0 + q0l * 8);
        *(uint4*)(sB  + r1l * STR + q1l * 8) = *(const uint4*)(Bw + (size_t)r1l * DIN + k0 + q1l * 8);
        __syncthreads();

#pragma unroll
        for (int ks = 0; ks < 2; ks++) {
            const int kb = ks * 16;
            uint32_t bb[4][2];
#pragma unroll
            for (int nt = 0; nt < 4; nt++) {
                const __nv_bfloat16* p = sB + (wn * 32 + nt * 8 + (lane >> 2)) * STR + kb + (lane & 3) * 2;
                bb[nt][0] = *(const uint32_t*)p;
                bb[nt][1] = *(const uint32_t*)(p + 8);
            }
            uint32_t av[4][4];
            // ---- hi pass ----
#pragma unroll
            for (int mt = 0; mt < 4; mt++) {
                const __nv_bfloat16* p = sAh + (wm * 64 + mt * 16 + (lane >> 2)) * STR + kb + (lane & 3) * 2;
                av[mt][0] = *(const uint32_t*)p;
                av[mt][1] = *(const uint32_t*)(p + 8 * STR);
                av[mt][2] = *(const uint32_t*)(p + 8);
                av[mt][3] = *(const uint32_t*)(p + 8 * STR + 8);
            }
#pragma unroll
            for (int mt = 0; mt < 4; mt++)
#pragma unroll
                for (int nt = 0; nt < 4; nt++) MMA(c[mt][nt], av[mt], bb[nt][0], bb[nt][1]);
            // ---- lo pass ----
#pragma unroll
            for (int mt = 0; mt < 4; mt++) {
                const __nv_bfloat16* p = sAl + (wm * 64 + mt * 16 + (lane >> 2)) * STR + kb + (lane & 3) * 2;
                av[mt][0] = *(const uint32_t*)p;
                av[mt][1] = *(const uint32_t*)(p + 8 * STR);
                av[mt][2] = *(const uint32_t*)(p + 8);
                av[mt][3] = *(const uint32_t*)(p + 8 * STR + 8);
            }
#pragma unroll
            for (int mt = 0; mt < 4; mt++)
#pragma unroll
                for (int nt = 0; nt < 4; nt++) MMA(c[mt][nt], av[mt], bb[nt][0], bb[nt][1]);
        }
        __syncthreads();
    }

    const float beta = g_beta;
#pragma unroll
    for (int mt = 0; mt < 4; mt++) {
        int r0 = m0 + wm * 64 + mt * 16 + (lane >> 2);
        float* c0p = C + (size_t)r0 * DOUT;
        float* c1p = C + (size_t)(r0 + 8) * DOUT;
#pragma unroll
        for (int nt = 0; nt < 4; nt++) {
            int cc = n0 + wn * 32 + nt * 8 + (lane & 3) * 2;
            float2 v0 = make_float2(c[mt][nt][0] * beta, c[mt][nt][1] * beta);
            float2 v1 = make_float2(c[mt][nt][2] * beta, c[mt][nt][3] * beta);
            *(float2*)(c0p + cc) = v0;
            *(float2*)(c1p + cc) = v1;
        }
    }
}

// ---------------- launch ------------------------------------------------------
extern "C" void kernel_launch(void* const* d_in, const int* in_sizes, int n_in,
                              void* d_out, int out_size) {
    const float* x = (const float*)d_in[0];
    const float* w = (const float*)d_in[1];
    // defensive: identify operands by element count
    if (n_in >= 2 && in_sizes[0] == DOUT * DIN && in_sizes[1] == MTOT * DIN) {
        const float* t = x; x = w; w = t;
    }
    float* out = (float*)d_out;

    kwsum<<<256, 256>>>((const float4*)w);
    kmu  <<<1, 256>>>();
    kbin <<<DOUT, 256>>>(w);
    kbeta<<<1, 1024>>>();
    kln  <<<MTOT, 256>>>(x);
    kgemm<<<dim3(DOUT / BN, MTOT / BM), 256>>>(out);
}

// round 5
// speedup vs baseline: 1.9855x; 1.9855x over previous
#include <cuda_runtime.h>
#include <cuda_fp16.h>
#include <cstdint>

#define DIN  4096
#define DOUT 4096
#define MTOT 8192

// ---------------- scratch ----------------------------------------------------
__device__ __align__(16) __half g_A[(size_t)MTOT * DIN];   // 64 MB fp16 x_norm
__device__ __align__(16) __half g_W[(size_t)DOUT * DIN];   // 32 MB fp16 sign(w-mu)
__device__ double g_psum[256];
__device__ double g_pabs[DOUT];
__device__ float  g_mu;
__device__ float  g_beta;

// ---------------- PTX helpers ------------------------------------------------
__device__ __forceinline__ uint32_t smem_u32(const void* p) {
    uint32_t a;
    asm("{ .reg .u64 t; cvta.to.shared.u64 t, %1; cvt.u32.u64 %0, t; }" : "=r"(a) : "l"(p));
    return a;
}
__device__ __forceinline__ void cp16(uint32_t dst, const void* src) {
    asm volatile("cp.async.cg.shared.global [%0], [%1], 16;\n" :: "r"(dst), "l"(src));
}
__device__ __forceinline__ void cp_commit() { asm volatile("cp.async.commit_group;\n"); }
template <int N>
__device__ __forceinline__ void cp_wait() { asm volatile("cp.async.wait_group %0;\n" :: "n"(N)); }

#define LDSM4(R0, R1, R2, R3, ADDR) \
    asm volatile("ldmatrix.sync.aligned.m8n8.x4.shared.b16 {%0,%1,%2,%3}, [%4];" \
                 : "=r"(R0), "=r"(R1), "=r"(R2), "=r"(R3) : "r"(ADDR))

#define MMA(C, A, B0, B1) asm volatile( \
    "mma.sync.aligned.m16n8k16.row.col.f32.f16.f16.f32 " \
    "{%0,%1,%2,%3},{%4,%5,%6,%7},{%8,%9},{%0,%1,%2,%3};\n" \
    : "+f"(C[0]), "+f"(C[1]), "+f"(C[2]), "+f"(C[3]) \
    : "r"(A[0]), "r"(A[1]), "r"(A[2]), "r"(A[3]), "r"(B0), "r"(B1))

// ---------------- 1) weight mean (fp64, deterministic) -----------------------
__global__ __launch_bounds__(256) void kwsum(const float4* __restrict__ w) {
    int t = blockIdx.x * 256 + threadIdx.x;
    double acc = 0.0;
#pragma unroll 4
    for (int i = 0; i < 64; i++) {
        float4 v = w[t + i * 65536];
        acc += (double)v.x + (double)v.y + (double)v.z + (double)v.w;
    }
    __shared__ double sd[256];
    sd[threadIdx.x] = acc; __syncthreads();
    for (int s = 128; s > 0; s >>= 1) {
        if (threadIdx.x < s) sd[threadIdx.x] += sd[threadIdx.x + s];
        __syncthreads();
    }
    if (threadIdx.x == 0) g_psum[blockIdx.x] = sd[0];
}
__global__ void kmu() {
    __shared__ double sd[256];
    sd[threadIdx.x] = g_psum[threadIdx.x]; __syncthreads();
    for (int s = 128; s > 0; s >>= 1) {
        if (threadIdx.x < s) sd[threadIdx.x] += sd[threadIdx.x + s];
        __syncthreads();
    }
    if (threadIdx.x == 0) g_mu = (float)(sd[0] * (1.0 / 16777216.0));
}

// ---------------- 2) binarize (fp16) + |w-mu| sums ---------------------------
__global__ __launch_bounds__(256) void kbin(const float* __restrict__ w) {
    int row = blockIdx.x, tid = threadIdx.x;
    float mu = g_mu;
    const float4* wr = (const float4*)(w + (size_t)row * DIN);
    uint2* wb = (uint2*)(g_W + (size_t)row * DIN);
    double acc = 0.0;
#pragma unroll
    for (int j = 0; j < 4; j++) {
        int idx = tid + j * 256;
        float4 v = wr[idx];
        float d0 = v.x - mu, d1 = v.y - mu, d2 = v.z - mu, d3 = v.w - mu;
        acc += (double)fabsf(d0) + (double)fabsf(d1) + (double)fabsf(d2) + (double)fabsf(d3);
        float s0 = (d0 > 0.f) ? 1.f : ((d0 < 0.f) ? -1.f : 0.f);
        float s1 = (d1 > 0.f) ? 1.f : ((d1 < 0.f) ? -1.f : 0.f);
        float s2 = (d2 > 0.f) ? 1.f : ((d2 < 0.f) ? -1.f : 0.f);
        float s3 = (d3 > 0.f) ? 1.f : ((d3 < 0.f) ? -1.f : 0.f);
        __half2 p0 = __floats2half2_rn(s0, s1);
        __half2 p1 = __floats2half2_rn(s2, s3);
        uint2 o;
        o.x = *reinterpret_cast<uint32_t*>(&p0);
        o.y = *reinterpret_cast<uint32_t*>(&p1);
        wb[idx] = o;
    }
    __shared__ double sd[256];
    sd[tid] = acc; __syncthreads();
    for (int s = 128; s > 0; s >>= 1) {
        if (tid < s) sd[tid] += sd[tid + s];
        __syncthreads();
    }
    if (tid == 0) g_pabs[row] = sd[0];
}
__global__ void kbeta() {
    __shared__ double sd[1024];
    int t = threadIdx.x;
    sd[t] = g_pabs[t] + g_pabs[t + 1024] + g_pabs[t + 2048] + g_pabs[t + 3072];
    __syncthreads();
    for (int s = 512; s > 0; s >>= 1) {
        if (t < s) sd[t] += sd[t + s];
        __syncthreads();
    }
    if (t == 0) g_beta = (float)(sd[0] * (1.0 / 16777216.0));
}

// ---------------- 3) LayerNorm -> fp16 ---------------------------------------
__global__ __launch_bounds__(256) void kln(const float* __restrict__ x) {
    int row = blockIdx.x, tid = threadIdx.x;
    const float4* xr = (const float4*)(x + (size_t)row * DIN);
    float4 v[4];
    float s = 0.f, ss = 0.f;
#pragma unroll
    for (int j = 0; j < 4; j++) {
        v[j] = xr[tid + j * 256];
        s  += v[j].x + v[j].y + v[j].z + v[j].w;
        ss += v[j].x * v[j].x + v[j].y * v[j].y + v[j].z * v[j].z + v[j].w * v[j].w;
    }
#pragma unroll
    for (int o = 16; o > 0; o >>= 1) {
        s  += __shfl_down_sync(0xffffffffu, s,  o);
        ss += __shfl_down_sync(0xffffffffu, ss, o);
    }
    __shared__ float sh_s[8], sh_ss[8];
    if ((tid & 31) == 0) { sh_s[tid >> 5] = s; sh_ss[tid >> 5] = ss; }
    __syncthreads();
    float ts = 0.f, tss = 0.f;
#pragma unroll
    for (int i = 0; i < 8; i++) { ts += sh_s[i]; tss += sh_ss[i]; }
    float mu   = ts * (1.f / 4096.f);
    float var  = tss * (1.f / 4096.f) - mu * mu;
    float rstd = rsqrtf(var + 1e-5f);

    uint2* ph = (uint2*)(g_A + (size_t)row * DIN);
#pragma unroll
    for (int j = 0; j < 4; j++) {
        int idx = tid + j * 256;
        __half2 p0 = __floats2half2_rn((v[j].x - mu) * rstd, (v[j].y - mu) * rstd);
        __half2 p1 = __floats2half2_rn((v[j].z - mu) * rstd, (v[j].w - mu) * rstd);
        uint2 o;
        o.x = *reinterpret_cast<uint32_t*>(&p0);
        o.y = *reinterpret_cast<uint32_t*>(&p1);
        ph[idx] = o;
    }
}

// ---------------- 4) GEMM: mma.sync fp16, cp.async 3-stage pipeline ----------
#define BM 128
#define BN 128
#define BK 64                       // fp16 -> 128 B rows
#define NST 3
#define NCHUNK (DIN / BK)           // 64
#define A_BYTES (BM * 128)          // 16 KB
#define STAGE   (2 * A_BYTES)       // 32 KB (A + B)
#define SMEM_DYN (NST * STAGE)      // 96 KB

__device__ __forceinline__ void load_stage(uint32_t sbase, const __half* Ag,
                                           const __half* Bg, int k0, int t) {
    const int r  = t >> 1;               // 0..127
    const int cb = (t & 1) * 4;          // 16B-chunk base
    const __half* Arow = Ag + (size_t)r * DIN + k0;
    const __half* Brow = Bg + (size_t)r * DIN + k0;
    const uint32_t dA = sbase + r * 128;
    const uint32_t dB = dA + A_BYTES;
#pragma unroll
    for (int i = 0; i < 4; i++) {
        const int c  = cb + i;
        const int ph = ((c ^ (r & 7)) << 4);    // SW128-style XOR swizzle
        cp16(dA + ph, Arow + c * 8);
        cp16(dB + ph, Brow + c * 8);
    }
}

__global__ __launch_bounds__(256, 2) void kgemm(float* __restrict__ C) {
    extern __shared__ __align__(1024) char dsm[];
    const uint32_t smem = smem_u32(dsm);

    const int tid  = threadIdx.x;
    const int lane = tid & 31;
    const int warp = tid >> 5;
    const int wm = warp >> 2;           // 0..1 -> 64 rows
    const int wn = warp & 3;            // 0..3 -> 32 cols
    const int m0 = blockIdx.y * BM;
    const int n0 = blockIdx.x * BN;

    const __half* Ag = g_A + (size_t)m0 * DIN;
    const __half* Bg = g_W + (size_t)n0 * DIN;

    float c[4][4][4];
#pragma unroll
    for (int a = 0; a < 4; a++)
#pragma unroll
        for (int b = 0; b < 4; b++)
#pragma unroll
            for (int d = 0; d < 4; d++) c[a][b][d] = 0.f;

    // precomputed ldmatrix lane geometry
    const int aRow = wm * 64 + (lane & 7) + ((lane >> 3) & 1) * 8;  // + mt*16
    const int aKg  = (lane >> 4);                                    // kc low bit sel
    const int bRow = wn * 32 + (lane & 7) + ((lane >> 4) & 1) * 8;  // + np*16
    const int bKg  = (lane >> 3) & 1;

    // prologue: stages 0,1
    load_stage(smem, Ag, Bg, 0, tid);  cp_commit();
    load_stage(smem + STAGE, Ag, Bg, BK, tid);  cp_commit();

    for (int ch = 0; ch < NCHUNK; ch++) {
        cp_wait<1>();
        __syncthreads();

        if (ch + 2 < NCHUNK)
            load_stage(smem + ((ch + 2) % NST) * STAGE, Ag, Bg, (ch + 2) * BK, tid);
        cp_commit();

        const uint32_t sA = smem + (ch % NST) * STAGE;
        const uint32_t sB = sA + A_BYTES;
#pragma unroll
        for (int ks = 0; ks < 4; ks++) {
            uint32_t a[4][4];
#pragma unroll
            for (int mt = 0; mt < 4; mt++) {
                const int r  = aRow + mt * 16;
                const int kc = ks * 2 + aKg;
                const uint32_t ad = sA + r * 128 + (((kc ^ (r & 7))) << 4);
                LDSM4(a[mt][0], a[mt][1], a[mt][2], a[mt][3], ad);
            }
            uint32_t b[4][2];
#pragma unroll
            for (int np = 0; np < 2; np++) {
                const int r  = bRow + np * 16;
                const int kc = ks * 2 + bKg;
                const uint32_t bd = sB + r * 128 + (((kc ^ (r & 7))) << 4);
                LDSM4(b[2 * np][0], b[2 * np][1], b[2 * np + 1][0], b[2 * np + 1][1], bd);
            }
#pragma unroll
            for (int mt = 0; mt < 4; mt++)
#pragma unroll
                for (int nt = 0; nt < 4; nt++)
                    MMA(c[mt][nt], a[mt], b[nt][0], b[nt][1]);
        }
    }

    // epilogue
    const float beta = g_beta;
#pragma unroll
    for (int mt = 0; mt < 4; mt++) {
        const int r0 = m0 + wm * 64 + mt * 16 + (lane >> 2);
        float* c0p = C + (size_t)r0 * DOUT;
        float* c1p = C + (size_t)(r0 + 8) * DOUT;
#pragma unroll
        for (int nt = 0; nt < 4; nt++) {
            const int cc = n0 + wn * 32 + nt * 8 + (lane & 3) * 2;
            *(float2*)(c0p + cc) = make_float2(c[mt][nt][0] * beta, c[mt][nt][1] * beta);
            *(float2*)(c1p + cc) = make_float2(c[mt][nt][2] * beta, c[mt][nt][3] * beta);
        }
    }
}

// ---------------- launch ------------------------------------------------------
extern "C" void kernel_launch(void* const* d_in, const int* in_sizes, int n_in,
                              void* d_out, int out_size) {
    const float* x = (const float*)d_in[0];
    const float* w = (const float*)d_in[1];
    if (n_in >= 2 && in_sizes[0] == DOUT * DIN && in_sizes[1] == MTOT * DIN) {
        const float* t = x; x = w; w = t;
    }
    float* out = (float*)d_out;

    static bool attr_set = false;
    if (!attr_set) {
        cudaFuncSetAttribute(kgemm, cudaFuncAttributeMaxDynamicSharedMemorySize, SMEM_DYN);
        attr_set = true;
    }

    kwsum<<<256, 256>>>((const float4*)w);
    kmu  <<<1, 256>>>();
    kbin <<<DOUT, 256>>>(w);
    kbeta<<<1, 1024>>>();
    kln  <<<MTOT, 256>>>(x);
    kgemm<<<dim3(DOUT / BN, MTOT / BM), 256, SMEM_DYN>>>(out);
}

// round 8
// speedup vs baseline: 2.1295x; 1.0725x over previous
#include <cuda_runtime.h>
#include <cuda_fp16.h>
#include <cstdint>

#define DIN  4096
#define DOUT 4096
#define MTOT 8192

// ---------------- scratch ----------------------------------------------------
__device__ __align__(16) __half g_A[(size_t)MTOT * DIN];   // 64 MB fp16 x_norm
__device__ __align__(16) __half g_W[(size_t)DOUT * DIN];   // 32 MB fp16 sign(w-mu)
__device__ double g_psum[256];
__device__ double g_pabs[DOUT];
__device__ float  g_mu;
__device__ float  g_beta;

// ---------------- PTX helpers ------------------------------------------------
__device__ __forceinline__ uint32_t smem_u32(const void* p) {
    uint32_t a;
    asm("{ .reg .u64 t; cvta.to.shared.u64 t, %1; cvt.u32.u64 %0, t; }" : "=r"(a) : "l"(p));
    return a;
}
__device__ __forceinline__ void cp16(uint32_t dst, const void* src) {
    asm volatile("cp.async.cg.shared.global [%0], [%1], 16;\n" :: "r"(dst), "l"(src));
}
__device__ __forceinline__ void cp_commit() { asm volatile("cp.async.commit_group;\n"); }
template <int N>
__device__ __forceinline__ void cp_wait() { asm volatile("cp.async.wait_group %0;\n" :: "n"(N)); }

#define LDSM4(R0, R1, R2, R3, ADDR) \
    asm volatile("ldmatrix.sync.aligned.m8n8.x4.shared.b16 {%0,%1,%2,%3}, [%4];" \
                 : "=r"(R0), "=r"(R1), "=r"(R2), "=r"(R3) : "r"(ADDR))

#define MMA(C, A, B0, B1) asm volatile( \
    "mma.sync.aligned.m16n8k16.row.col.f32.f16.f16.f32 " \
    "{%0,%1,%2,%3},{%4,%5,%6,%7},{%8,%9},{%0,%1,%2,%3};\n" \
    : "+f"(C[0]), "+f"(C[1]), "+f"(C[2]), "+f"(C[3]) \
    : "r"(A[0]), "r"(A[1]), "r"(A[2]), "r"(A[3]), "r"(B0), "r"(B1))

// ---------------- 1) weight mean (fp64, deterministic) -----------------------
__global__ __launch_bounds__(256) void kwsum(const float4* __restrict__ w) {
    int t = blockIdx.x * 256 + threadIdx.x;
    double acc = 0.0;
#pragma unroll 4
    for (int i = 0; i < 64; i++) {
        float4 v = w[t + i * 65536];
        acc += (double)v.x + (double)v.y + (double)v.z + (double)v.w;
    }
    __shared__ double sd[256];
    sd[threadIdx.x] = acc; __syncthreads();
    for (int s = 128; s > 0; s >>= 1) {
        if (threadIdx.x < s) sd[threadIdx.x] += sd[threadIdx.x + s];
        __syncthreads();
    }
    if (threadIdx.x == 0) g_psum[blockIdx.x] = sd[0];
}
__global__ void kmu() {
    __shared__ double sd[256];
    sd[threadIdx.x] = g_psum[threadIdx.x]; __syncthreads();
    for (int s = 128; s > 0; s >>= 1) {
        if (threadIdx.x < s) sd[threadIdx.x] += sd[threadIdx.x + s];
        __syncthreads();
    }
    if (threadIdx.x == 0) g_mu = (float)(sd[0] * (1.0 / 16777216.0));
}

// ---------------- 2) binarize (fp16) + |w-mu| sums ---------------------------
__global__ __launch_bounds__(256) void kbin(const float* __restrict__ w) {
    int row = blockIdx.x, tid = threadIdx.x;
    float mu = g_mu;
    const float4* wr = (const float4*)(w + (size_t)row * DIN);
    uint2* wb = (uint2*)(g_W + (size_t)row * DIN);
    double acc = 0.0;
#pragma unroll
    for (int j = 0; j < 4; j++) {
        int idx = tid + j * 256;
        float4 v = wr[idx];
        float d0 = v.x - mu, d1 = v.y - mu, d2 = v.z - mu, d3 = v.w - mu;
        acc += (double)fabsf(d0) + (double)fabsf(d1) + (double)fabsf(d2) + (double)fabsf(d3);
        float s0 = (d0 > 0.f) ? 1.f : ((d0 < 0.f) ? -1.f : 0.f);
        float s1 = (d1 > 0.f) ? 1.f : ((d1 < 0.f) ? -1.f : 0.f);
        float s2 = (d2 > 0.f) ? 1.f : ((d2 < 0.f) ? -1.f : 0.f);
        float s3 = (d3 > 0.f) ? 1.f : ((d3 < 0.f) ? -1.f : 0.f);
        __half2 p0 = __floats2half2_rn(s0, s1);
        __half2 p1 = __floats2half2_rn(s2, s3);
        uint2 o;
        o.x = *reinterpret_cast<uint32_t*>(&p0);
        o.y = *reinterpret_cast<uint32_t*>(&p1);
        wb[idx] = o;
    }
    __shared__ double sd[256];
    sd[tid] = acc; __syncthreads();
    for (int s = 128; s > 0; s >>= 1) {
        if (tid < s) sd[tid] += sd[tid + s];
        __syncthreads();
    }
    if (tid == 0) g_pabs[row] = sd[0];
}
__global__ void kbeta() {
    __shared__ double sd[1024];
    int t = threadIdx.x;
    sd[t] = g_pabs[t] + g_pabs[t + 1024] + g_pabs[t + 2048] + g_pabs[t + 3072];
    __syncthreads();
    for (int s = 512; s > 0; s >>= 1) {
        if (t < s) sd[t] += sd[t + s];
        __syncthreads();
    }
    if (t == 0) g_beta = (float)(sd[0] * (1.0 / 16777216.0));
}

// ---------------- 3) LayerNorm -> fp16 ---------------------------------------
__global__ __launch_bounds__(256) void kln(const float* __restrict__ x) {
    int row = blockIdx.x, tid = threadIdx.x;
    const float4* xr = (const float4*)(x + (size_t)row * DIN);
    float4 v[4];
    float s = 0.f, ss = 0.f;
#pragma unroll
    for (int j = 0; j < 4; j++) {
        v[j] = xr[tid + j * 256];
        s  += v[j].x + v[j].y + v[j].z + v[j].w;
        ss += v[j].x * v[j].x + v[j].y * v[j].y + v[j].z * v[j].z + v[j].w * v[j].w;
    }
#pragma unroll
    for (int o = 16; o > 0; o >>= 1) {
        s  += __shfl_down_sync(0xffffffffu, s,  o);
        ss += __shfl_down_sync(0xffffffffu, ss, o);
    }
    __shared__ float sh_s[8], sh_ss[8];
    if ((tid & 31) == 0) { sh_s[tid >> 5] = s; sh_ss[tid >> 5] = ss; }
    __syncthreads();
    float ts = 0.f, tss = 0.f;
#pragma unroll
    for (int i = 0; i < 8; i++) { ts += sh_s[i]; tss += sh_ss[i]; }
    float mu   = ts * (1.f / 4096.f);
    float var  = tss * (1.f / 4096.f) - mu * mu;
    float rstd = rsqrtf(var + 1e-5f);

    uint2* ph = (uint2*)(g_A + (size_t)row * DIN);
#pragma unroll
    for (int j = 0; j < 4; j++) {
        int idx = tid + j * 256;
        __half2 p0 = __floats2half2_rn((v[j].x - mu) * rstd, (v[j].y - mu) * rstd);
        __half2 p1 = __floats2half2_rn((v[j].z - mu) * rstd, (v[j].w - mu) * rstd);
        uint2 o;
        o.x = *reinterpret_cast<uint32_t*>(&p0);
        o.y = *reinterpret_cast<uint32_t*>(&p1);
        ph[idx] = o;
    }
}

// ---------------- 4) GEMM: BM=256 tile, 512 thr, 4-stage cp.async ------------
#define BM 256
#define BN 128
#define BK 64                       // fp16 -> 128 B rows
#define NST 4
#define NCHUNK (DIN / BK)           // 64
#define A_BYTES (BM * 128)          // 32 KB
#define B_BYTES (BN * 128)          // 16 KB
#define STAGE   (A_BYTES + B_BYTES) // 48 KB
#define SMEM_DYN (NST * STAGE)      // 192 KB

__device__ __forceinline__ void load_stage(uint32_t sbase, const __half* Ag,
                                           const __half* Bg, int k0, int t) {
    // A: 256 rows x 8 chunks = 2048 cp16; 512 threads -> 4 each
    {
        const int r  = t >> 1;               // 0..255
        const int cb = (t & 1) * 4;
        const __half* Arow = Ag + (size_t)r * DIN + k0;
        const uint32_t dA = sbase + r * 128;
#pragma unroll
        for (int i = 0; i < 4; i++) {
            const int c = cb + i;
            cp16(dA + ((c ^ (r & 7)) << 4), Arow + c * 8);
        }
    }
    // B: 128 rows x 8 chunks = 1024 cp16; 512 threads -> 2 each
    {
        const int r  = t >> 2;               // 0..127
        const int cb = (t & 3) * 2;
        const __half* Brow = Bg + (size_t)r * DIN + k0;
        const uint32_t dB = sbase + A_BYTES + r * 128;
#pragma unroll
        for (int i = 0; i < 2; i++) {
            const int c = cb + i;
            cp16(dB + ((c ^ (r & 7)) << 4), Brow + c * 8);
        }
    }
}

__global__ __launch_bounds__(512, 1) void kgemm(float* __restrict__ C) {
    extern __shared__ __align__(1024) char dsm[];
    const uint32_t smem = smem_u32(dsm);

    const int tid  = threadIdx.x;
    const int lane = tid & 31;
    const int warp = tid >> 5;
    const int wm = warp >> 2;           // 0..3 -> 64-row blocks
    const int wn = warp & 3;            // 0..3 -> 32-col blocks
    const int m0 = blockIdx.y * BM;
    const int n0 = blockIdx.x * BN;

    const __half* Ag = g_A + (size_t)m0 * DIN;
    const __half* Bg = g_W + (size_t)n0 * DIN;

    float c[4][4][4];
#pragma unroll
    for (int a = 0; a < 4; a++)
#pragma unroll
        for (int b = 0; b < 4; b++)
#pragma unroll
            for (int d = 0; d < 4; d++) c[a][b][d] = 0.f;

    // ldmatrix lane geometry
    const int aRow = wm * 64 + (lane & 7) + ((lane >> 3) & 1) * 8;  // + mt*16
    const int aKg  = (lane >> 4);
    const int bRow = wn * 32 + (lane & 7) + ((lane >> 4) & 1) * 8;  // + np*16
    const int bKg  = (lane >> 3) & 1;

    // prologue: stages 0,1,2
    load_stage(smem, Ag, Bg, 0, tid);               cp_commit();
    load_stage(smem + STAGE, Ag, Bg, BK, tid);      cp_commit();
    load_stage(smem + 2 * STAGE, Ag, Bg, 2 * BK, tid); cp_commit();

    for (int ch = 0; ch < NCHUNK; ch++) {
        cp_wait<2>();
        __syncthreads();

        if (ch + 3 < NCHUNK)
            load_stage(smem + ((ch + 3) & 3) * STAGE, Ag, Bg, (ch + 3) * BK, tid);
        cp_commit();

        const uint32_t sA = smem + (ch & 3) * STAGE;
        const uint32_t sB = sA + A_BYTES;
#pragma unroll
        for (int ks = 0; ks < 4; ks++) {
            uint32_t a[4][4];
#pragma unroll
            for (int mt = 0; mt < 4; mt++) {
                const int r  = aRow + mt * 16;
                const int kc = ks * 2 + aKg;
                LDSM4(a[mt][0], a[mt][1], a[mt][2], a[mt][3],
                      sA + r * 128 + (((kc ^ (r & 7))) << 4));
            }
            uint32_t b[4][2];
#pragma unroll
            for (int np = 0; np < 2; np++) {
                const int r  = bRow + np * 16;
                const int kc = ks * 2 + bKg;
                LDSM4(b[2 * np][0], b[2 * np][1], b[2 * np + 1][0], b[2 * np + 1][1],
                      sB + r * 128 + (((kc ^ (r & 7))) << 4));
            }
#pragma unroll
            for (int mt = 0; mt < 4; mt++)
#pragma unroll
                for (int nt = 0; nt < 4; nt++)
                    MMA(c[mt][nt], a[mt], b[nt][0], b[nt][1]);
        }
    }

    // epilogue
    const float beta = g_beta;
#pragma unroll
    for (int mt = 0; mt < 4; mt++) {
        const int r0 = m0 + wm * 64 + mt * 16 + (lane >> 2);
        float* c0p = C + (size_t)r0 * DOUT;
        float* c1p = C + (size_t)(r0 + 8) * DOUT;
#pragma unroll
        for (int nt = 0; nt < 4; nt++) {
            const int cc = n0 + wn * 32 + nt * 8 + (lane & 3) * 2;
            *(float2*)(c0p + cc) = make_float2(c[mt][nt][0] * beta, c[mt][nt][1] * beta);
            *(float2*)(c1p + cc) = make_float2(c[mt][nt][2] * beta, c[mt][nt][3] * beta);
        }
    }
}

// ---------------- launch ------------------------------------------------------
extern "C" void kernel_launch(void* const* d_in, const int* in_sizes, int n_in,
                              void* d_out, int out_size) {
    const float* x = (const float*)d_in[0];
    const float* w = (const float*)d_in[1];
    if (n_in >= 2 && in_sizes[0] == DOUT * DIN && in_sizes[1] == MTOT * DIN) {
        const float* t = x; x = w; w = t;
    }
    float* out = (float*)d_out;

    static bool attr_set = false;
    if (!attr_set) {
        cudaFuncSetAttribute(kgemm, cudaFuncAttributeMaxDynamicSharedMemorySize, SMEM_DYN);
        attr_set = true;
    }

    kwsum<<<256, 256>>>((const float4*)w);
    kmu  <<<1, 256>>>();
    kbin <<<DOUT, 256>>>(w);
    kbeta<<<1, 1024>>>();
    kln  <<<MTOT, 256>>>(x);
    kgemm<<<dim3(DOUT / BN, MTOT / BM), 512, SMEM_DYN>>>(out);
}